// round 1
// baseline (speedup 1.0000x reference)
#include <cuda_runtime.h>
#include <cstdint>

#define NMAX 100000
#define EMAX 1600000
#define HID 128

// ---------------- scratch (device globals; no allocations allowed) ----------
__device__ float g_event_feat[(size_t)NMAX * HID];
__device__ float g_xg[(size_t)NMAX * HID];
__device__ float g_diffused[(size_t)NMAX * HID];
__device__ float g_corrected[(size_t)NMAX * HID];
__device__ int   g_deg[NMAX];       // edge count into node (excl. self loop)
__device__ float g_dis[NMAX];       // 1/sqrt(deg+1)
__device__ int   g_rowstart[NMAX];
__device__ int   g_cursor[NMAX];
__device__ int   g_csr[EMAX];
__device__ int   g_bsum[1024];
__device__ int   g_is64;

// ---------------- packed f32x2 FMA ------------------------------------------
union F2 { float2 f; unsigned long long u; };
__device__ __forceinline__ void fma2(F2& d, const F2& a, const F2& b) {
    asm("fma.rn.f32x2 %0, %1, %2, %0;" : "+l"(d.u) : "l"(a.u), "l"(b.u));
}

enum { EPI_RELU = 0, EPI_NONE = 1, EPI_GATE = 2 };

// C[M,128] = epi( concat(A0[:,0:K0], A1[:,K0:KTOT]) @ W[KTOT,128] + bias )
// EPI_GATE: g = sigmoid(.); C = E0*(1-g) + E1*g
template<int KTOT, int K0, int EPI>
__global__ void __launch_bounds__(256)
gemm128(const float* __restrict__ A0, const float* __restrict__ A1,
        const float* __restrict__ W,  const float* __restrict__ bias,
        const float* __restrict__ E0, const float* __restrict__ E1,
        float* __restrict__ C, int M)
{
    constexpr int BM = 64, BK = 16;
    __shared__ float As[BK][BM];
    __shared__ float Bs[BK][HID];

    const int tid  = threadIdx.x;
    const int m0   = blockIdx.x * BM;
    const int arow = tid >> 2;            // 0..63
    const int aq   = (tid & 3) * 4;       // k offset within tile
    const int brow = tid >> 4;            // 0..15
    const int bcol = (tid & 15) * 8;
    const int tn   = tid & 15;            // 8 output cols
    const int tm   = tid >> 4;            // 4 output rows
    const int col0 = tn * 8;
    const int row0 = tm * 4;

    F2 acc[4][4];
#pragma unroll
    for (int r = 0; r < 4; r++)
#pragma unroll
        for (int c = 0; c < 4; c++) acc[r][c].f = make_float2(0.f, 0.f);

    for (int kb = 0; kb < KTOT; kb += BK) {
        // --- load A tile (64 x 16), transposed into As[k][m]
        const float* Ap; int kc, stride;
        if (KTOT == K0 || kb < K0) { Ap = A0; kc = kb;      stride = K0; }
        else                       { Ap = A1; kc = kb - K0; stride = KTOT - K0; }
        const int ar = m0 + arow;
        float4 av = make_float4(0.f, 0.f, 0.f, 0.f);
        if (ar < M) av = *(const float4*)(Ap + (size_t)ar * stride + kc + aq);
        As[aq + 0][arow] = av.x; As[aq + 1][arow] = av.y;
        As[aq + 2][arow] = av.z; As[aq + 3][arow] = av.w;

        // --- load B tile (16 x 128)
        const float4* wp = (const float4*)(W + (size_t)(kb + brow) * HID + bcol);
        float4 w0 = wp[0], w1 = wp[1];
        *(float4*)&Bs[brow][bcol]     = w0;
        *(float4*)&Bs[brow][bcol + 4] = w1;
        __syncthreads();

#pragma unroll
        for (int k = 0; k < BK; k++) {
            float4 a4 = *(const float4*)&As[k][row0];
            F2 aa[4];
            aa[0].f = make_float2(a4.x, a4.x); aa[1].f = make_float2(a4.y, a4.y);
            aa[2].f = make_float2(a4.z, a4.z); aa[3].f = make_float2(a4.w, a4.w);
            float4 b0 = *(const float4*)&Bs[k][col0];
            float4 b1 = *(const float4*)&Bs[k][col0 + 4];
            F2 bb[4];
            bb[0].f = make_float2(b0.x, b0.y); bb[1].f = make_float2(b0.z, b0.w);
            bb[2].f = make_float2(b1.x, b1.y); bb[3].f = make_float2(b1.z, b1.w);
#pragma unroll
            for (int r = 0; r < 4; r++)
#pragma unroll
                for (int c = 0; c < 4; c++) fma2(acc[r][c], aa[r], bb[c]);
        }
        __syncthreads();
    }

    // --- epilogue
    float bb8[8] = {0, 0, 0, 0, 0, 0, 0, 0};
    if (EPI != EPI_NONE) {
        float4 bv0 = *(const float4*)(bias + col0);
        float4 bv1 = *(const float4*)(bias + col0 + 4);
        bb8[0] = bv0.x; bb8[1] = bv0.y; bb8[2] = bv0.z; bb8[3] = bv0.w;
        bb8[4] = bv1.x; bb8[5] = bv1.y; bb8[6] = bv1.z; bb8[7] = bv1.w;
    }
#pragma unroll
    for (int r = 0; r < 4; r++) {
        const int grow = m0 + row0 + r;
        if (grow >= M) continue;
        float v[8];
#pragma unroll
        for (int c = 0; c < 4; c++) { v[2*c] = acc[r][c].f.x; v[2*c+1] = acc[r][c].f.y; }
        float out[8];
        if (EPI == EPI_RELU) {
#pragma unroll
            for (int j = 0; j < 8; j++) out[j] = fmaxf(v[j] + bb8[j], 0.f);
        } else if (EPI == EPI_NONE) {
#pragma unroll
            for (int j = 0; j < 8; j++) out[j] = v[j];
        } else { // EPI_GATE
            float4 e0a = *(const float4*)(E0 + (size_t)grow * HID + col0);
            float4 e0b = *(const float4*)(E0 + (size_t)grow * HID + col0 + 4);
            float4 e1a = *(const float4*)(E1 + (size_t)grow * HID + col0);
            float4 e1b = *(const float4*)(E1 + (size_t)grow * HID + col0 + 4);
            float e0[8] = {e0a.x, e0a.y, e0a.z, e0a.w, e0b.x, e0b.y, e0b.z, e0b.w};
            float e1[8] = {e1a.x, e1a.y, e1a.z, e1a.w, e1b.x, e1b.y, e1b.z, e1b.w};
#pragma unroll
            for (int j = 0; j < 8; j++) {
                float g = 1.f / (1.f + __expf(-(v[j] + bb8[j])));
                out[j] = e0[j] + (e1[j] - e0[j]) * g;
            }
        }
        *(float4*)(C + (size_t)grow * HID + col0)     = make_float4(out[0], out[1], out[2], out[3]);
        *(float4*)(C + (size_t)grow * HID + col0 + 4) = make_float4(out[4], out[5], out[6], out[7]);
    }
}

// ---------------- edge-index dtype sniff -------------------------------------
// int64 node ids < 2^31 => every odd 32-bit word is 0. If any is nonzero => int32.
__global__ void detect_idx(const unsigned int* __restrict__ p, int E2) {
    __shared__ int any;
    if (threadIdx.x == 0) any = 0;
    __syncthreads();
    int nsamp = E2 / 2; if (nsamp > 2048) nsamp = 2048;
    for (int i = threadIdx.x; i < nsamp; i += blockDim.x)
        if (p[2 * i + 1] != 0u) atomicOr(&any, 1);
    __syncthreads();
    if (threadIdx.x == 0) g_is64 = any ? 0 : 1;
}

__device__ __forceinline__ int edge_val(const void* ei, size_t idx) {
    return g_is64 ? (int)((const long long*)ei)[idx] : ((const int*)ei)[idx];
}

// ---------------- degree / CSR ------------------------------------------------
__global__ void init_deg(int n) {
    int i = blockIdx.x * blockDim.x + threadIdx.x;
    if (i < n) g_deg[i] = 0;
}
__global__ void count_deg(const void* __restrict__ ei, int E) {
    int e = blockIdx.x * blockDim.x + threadIdx.x;
    if (e >= E) return;
    int d = edge_val(ei, (size_t)E + e);
    atomicAdd(&g_deg[d], 1);
}
__global__ void compute_dis(int n) {
    int i = blockIdx.x * blockDim.x + threadIdx.x;
    if (i < n) g_dis[i] = rsqrtf((float)(g_deg[i] + 1));
}
// scan stage 1: per-block (512) sums of g_deg
__global__ void scan1(int n) {
    __shared__ int sh[512];
    int i = blockIdx.x * 512 + threadIdx.x;
    sh[threadIdx.x] = (i < n) ? g_deg[i] : 0;
    __syncthreads();
    for (int off = 256; off > 0; off >>= 1) {
        if (threadIdx.x < off) sh[threadIdx.x] += sh[threadIdx.x + off];
        __syncthreads();
    }
    if (threadIdx.x == 0) g_bsum[blockIdx.x] = sh[0];
}
// scan stage 2: exclusive scan of block sums (single block, nb <= 1024)
__global__ void scan2(int nb) {
    __shared__ int sh[1024];
    int tid = threadIdx.x;
    int v = (tid < nb) ? g_bsum[tid] : 0;
    sh[tid] = v;
    __syncthreads();
    for (int off = 1; off < 1024; off <<= 1) {
        int t = (tid >= off) ? sh[tid - off] : 0;
        __syncthreads();
        sh[tid] += t;
        __syncthreads();
    }
    if (tid < nb) g_bsum[tid] = sh[tid] - v;  // exclusive
}
// scan stage 3: within-block exclusive scan + offset -> rowstart, cursor
__global__ void scan3(int n) {
    __shared__ int sh[512];
    int tid = threadIdx.x;
    int i = blockIdx.x * 512 + tid;
    int v = (i < n) ? g_deg[i] : 0;
    sh[tid] = v;
    __syncthreads();
    for (int off = 1; off < 512; off <<= 1) {
        int t = (tid >= off) ? sh[tid - off] : 0;
        __syncthreads();
        sh[tid] += t;
        __syncthreads();
    }
    if (i < n) {
        int rs = g_bsum[blockIdx.x] + sh[tid] - v;
        g_rowstart[i] = rs;
        g_cursor[i]   = rs;
    }
}
__global__ void fill_csr(const void* __restrict__ ei, int E) {
    int e = blockIdx.x * blockDim.x + threadIdx.x;
    if (e >= E) return;
    int s = edge_val(ei, e);
    int d = edge_val(ei, (size_t)E + e);
    int pos = atomicAdd(&g_cursor[d], 1);
    g_csr[pos] = s;
}

// ---------------- aggregation: warp per node, gather-sum ----------------------
__global__ void aggregate(const float* __restrict__ b_gcn, int n) {
    int gw   = (blockIdx.x * blockDim.x + threadIdx.x) >> 5;
    int lane = threadIdx.x & 31;
    if (gw >= n) return;
    const int node = gw;
    const float4* __restrict__ xg4 = (const float4*)g_xg;

    float4 selfv = xg4[(size_t)node * 32 + lane];
    float  dn    = g_dis[node];
    int    s0    = g_rowstart[node];
    int    cnt   = g_deg[node];

    float4 acc = make_float4(0.f, 0.f, 0.f, 0.f);
    int e = s0, eend = s0 + cnt;
    for (; e + 1 < eend; e += 2) {
        int s1 = g_csr[e], s2 = g_csr[e + 1];
        float w1 = g_dis[s1], w2 = g_dis[s2];
        float4 v1 = xg4[(size_t)s1 * 32 + lane];
        float4 v2 = xg4[(size_t)s2 * 32 + lane];
        acc.x += v1.x * w1 + v2.x * w2;
        acc.y += v1.y * w1 + v2.y * w2;
        acc.z += v1.z * w1 + v2.z * w2;
        acc.w += v1.w * w1 + v2.w * w2;
    }
    if (e < eend) {
        int s1 = g_csr[e];
        float w1 = g_dis[s1];
        float4 v1 = xg4[(size_t)s1 * 32 + lane];
        acc.x += v1.x * w1; acc.y += v1.y * w1;
        acc.z += v1.z * w1; acc.w += v1.w * w1;
    }
    const float sw = dn * dn;  // self-loop norm = 1/deg
    float4 b = ((const float4*)b_gcn)[lane];
    float4 o;
    o.x = fmaxf(acc.x * dn + selfv.x * sw + b.x, 0.f);
    o.y = fmaxf(acc.y * dn + selfv.y * sw + b.y, 0.f);
    o.z = fmaxf(acc.z * dn + selfv.z * sw + b.z, 0.f);
    o.w = fmaxf(acc.w * dn + selfv.w * sw + b.w, 0.f);
    ((float4*)g_diffused)[(size_t)node * 32 + lane] = o;
}

// ---------------- launcher -----------------------------------------------------
extern "C" void kernel_launch(void* const* d_in, const int* in_sizes, int n_in,
                              void* d_out, int out_size)
{
    const float* base   = (const float*)d_in[0];
    const float* ev     = (const float*)d_in[1];
    const void*  ei     = d_in[2];
    const float* W_proj = (const float*)d_in[3];
    const float* b_proj = (const float*)d_in[4];
    const float* W_gcn  = (const float*)d_in[5];
    const float* b_gcn  = (const float*)d_in[6];
    const float* W_gate = (const float*)d_in[7];
    const float* b_gate = (const float*)d_in[8];
    const float* W_fuse = (const float*)d_in[9];
    const float* b_fuse = (const float*)d_in[10];

    const int N = in_sizes[0] / HID;
    const int E = in_sizes[2] / 2;

    float *p_ef, *p_xg, *p_diff, *p_corr;
    cudaGetSymbolAddress((void**)&p_ef,   g_event_feat);
    cudaGetSymbolAddress((void**)&p_xg,   g_xg);
    cudaGetSymbolAddress((void**)&p_diff, g_diffused);
    cudaGetSymbolAddress((void**)&p_corr, g_corrected);

    const int gM = (N + 63) / 64;
    const int gN = (N + 255) / 256;
    const int gE = (E + 255) / 256;
    const int nb = (N + 511) / 512;

    // dtype sniff for edge_index (int64 vs int32)
    detect_idx<<<1, 256>>>((const unsigned int*)ei, 2 * E);

    // event_feat = relu(ev @ W_proj + b_proj)
    gemm128<64, 64, EPI_RELU><<<gM, 256>>>(ev, nullptr, W_proj, b_proj,
                                           nullptr, nullptr, p_ef, N);
    // xg = event_feat @ W_gcn
    gemm128<128, 128, EPI_NONE><<<gM, 256>>>(p_ef, nullptr, W_gcn, nullptr,
                                             nullptr, nullptr, p_xg, N);
    // degrees + CSR
    init_deg<<<gN, 256>>>(N);
    count_deg<<<gE, 256>>>(ei, E);
    compute_dis<<<gN, 256>>>(N);
    scan1<<<nb, 512>>>(N);
    scan2<<<1, 1024>>>(nb);
    scan3<<<nb, 512>>>(N);
    fill_csr<<<gE, 256>>>(ei, E);

    // diffused = relu(scatter-sum + b_gcn)   (gather-sum form, warp per node)
    aggregate<<<(N * 32 + 255) / 256, 256>>>(b_gcn, N);

    // gate + corrected
    gemm128<256, 128, EPI_GATE><<<gM, 256>>>(base, p_diff, W_gate, b_gate,
                                             base, p_diff, p_corr, N);
    // out = relu([base, corrected] @ W_fuse + b_fuse)
    gemm128<256, 128, EPI_RELU><<<gM, 256>>>(base, p_corr, W_fuse, b_fuse,
                                             nullptr, nullptr, (float*)d_out, N);
}